// round 1
// baseline (speedup 1.0000x reference)
#include <cuda_runtime.h>
#include <math.h>

typedef unsigned long long ull_t;

// ---------------------------------------------------------------------------
// packed f32x2 helpers (B300: FFMA2 doubles fp32 fma-pipe throughput; ptxas
// never emits it from C++, only via PTX fma.rn.f32x2)
// ---------------------------------------------------------------------------
__device__ __forceinline__ ull_t pk2(float x, float y) {
    ull_t r;
    asm("mov.b64 %0, {%1, %2};" : "=l"(r) : "r"(__float_as_uint(x)), "r"(__float_as_uint(y)));
    return r;
}
__device__ __forceinline__ void fma2(ull_t& d, ull_t a, ull_t b) {
    asm("fma.rn.f32x2 %0, %1, %2, %0;" : "+l"(d) : "l"(a), "l"(b));
}
__device__ __forceinline__ ull_t add2(ull_t a, ull_t b) {
    ull_t r;
    asm("add.rn.f32x2 %0, %1, %2;" : "=l"(r) : "l"(a), "l"(b));
    return r;
}
__device__ __forceinline__ float sigf(float x) { return 1.0f / (1.0f + expf(-x)); }

// ---------------------------------------------------------------------------
// scratch (device globals — no allocation allowed)
// ---------------------------------------------------------------------------
__device__ float g_Gf[33554432];     // [T*B, 2048] fwd input-gate precompute (also reused as proj buffer)
__device__ float g_Gb[33554432];     // [T*B, 2048] bwd
__device__ float g_bufA[16777216];   // [T*B, 1024] layer activations ping
__device__ float g_bufB[16777216];   // [T*B, 1024] layer activations pong
__device__ float g_hst[131072];      // h double buffer: [parity][dir][64][512]
__device__ float g_cst[65536];       // c: [dir][64][512]

// ---------------------------------------------------------------------------
// C[M,N] = A[M,K] @ W[N,K]^T + bias[N]      (A,W row-major; M from gridDim.y)
// BM=BN=64, BK=16, 128 threads, per-thread 4m x 8n (f32x2-paired on n),
// double-buffered smem.
// ---------------------------------------------------------------------------
__global__ void __launch_bounds__(128) gemm_nt_bias(
    const float* __restrict__ A, const float* __restrict__ W,
    const float* __restrict__ bias, float* __restrict__ C,
    int N, int K)
{
    __shared__ float As[2][16][68];
    __shared__ float Ws[2][16][68];

    const int tid = threadIdx.x;
    const long m_base = (long)blockIdx.y * 64;
    const long n_base = (long)blockIdx.x * 64;

    // global-load mapping: items {tid, tid+128} over 64 rows x 4 float4-cols
    const int r0 = tid >> 2;            // 0..31
    const int q0 = tid & 3;             // float4 column within BK
    const int r1 = r0 + 32;             // 32..63

    const float* Arow0 = A + (m_base + r0) * (long)K + q0 * 4;
    const float* Arow1 = A + (m_base + r1) * (long)K + q0 * 4;
    const float* Wrow0 = W + (n_base + r0) * (long)K + q0 * 4;
    const float* Wrow1 = W + (n_base + r1) * (long)K + q0 * 4;

    const int tx  = tid & 7;            // n tile: 8 threads * 8 cols
    const int ty  = tid >> 3;           // m tile: 16 threads * 4 rows
    const int n0  = tx * 8;
    const int mm0 = ty * 4;

    ull_t acc[4][4];
#pragma unroll
    for (int i = 0; i < 4; ++i)
#pragma unroll
        for (int p = 0; p < 4; ++p) acc[i][p] = 0ull;

    float4 ra0, ra1, rw0, rw1;
    const int kq = q0 * 4;

    // preload chunk 0
    ra0 = *(const float4*)(Arow0);
    ra1 = *(const float4*)(Arow1);
    rw0 = *(const float4*)(Wrow0);
    rw1 = *(const float4*)(Wrow1);
    As[0][kq+0][r0] = ra0.x; As[0][kq+1][r0] = ra0.y; As[0][kq+2][r0] = ra0.z; As[0][kq+3][r0] = ra0.w;
    As[0][kq+0][r1] = ra1.x; As[0][kq+1][r1] = ra1.y; As[0][kq+2][r1] = ra1.z; As[0][kq+3][r1] = ra1.w;
    Ws[0][kq+0][r0] = rw0.x; Ws[0][kq+1][r0] = rw0.y; Ws[0][kq+2][r0] = rw0.z; Ws[0][kq+3][r0] = rw0.w;
    Ws[0][kq+0][r1] = rw1.x; Ws[0][kq+1][r1] = rw1.y; Ws[0][kq+2][r1] = rw1.z; Ws[0][kq+3][r1] = rw1.w;
    __syncthreads();

    const int nk = K >> 4;
    for (int cch = 0; cch < nk; ++cch) {
        const int buf = cch & 1;
        if (cch + 1 < nk) {
            const int k0 = (cch + 1) << 4;
            ra0 = *(const float4*)(Arow0 + k0);
            ra1 = *(const float4*)(Arow1 + k0);
            rw0 = *(const float4*)(Wrow0 + k0);
            rw1 = *(const float4*)(Wrow1 + k0);
        }
#pragma unroll
        for (int k = 0; k < 16; ++k) {
            float4 a = *(const float4*)&As[buf][k][mm0];
            ulonglong2 wv0 = *(const ulonglong2*)&Ws[buf][k][n0];
            ulonglong2 wv1 = *(const ulonglong2*)&Ws[buf][k][n0 + 4];
            ull_t a2[4];
            a2[0] = pk2(a.x, a.x); a2[1] = pk2(a.y, a.y);
            a2[2] = pk2(a.z, a.z); a2[3] = pk2(a.w, a.w);
            ull_t wr[4] = {wv0.x, wv0.y, wv1.x, wv1.y};
#pragma unroll
            for (int i = 0; i < 4; ++i) {
                fma2(acc[i][0], a2[i], wr[0]);
                fma2(acc[i][1], a2[i], wr[1]);
                fma2(acc[i][2], a2[i], wr[2]);
                fma2(acc[i][3], a2[i], wr[3]);
            }
        }
        if (cch + 1 < nk) {
            const int nb = buf ^ 1;
            As[nb][kq+0][r0] = ra0.x; As[nb][kq+1][r0] = ra0.y; As[nb][kq+2][r0] = ra0.z; As[nb][kq+3][r0] = ra0.w;
            As[nb][kq+0][r1] = ra1.x; As[nb][kq+1][r1] = ra1.y; As[nb][kq+2][r1] = ra1.z; As[nb][kq+3][r1] = ra1.w;
            Ws[nb][kq+0][r0] = rw0.x; Ws[nb][kq+1][r0] = rw0.y; Ws[nb][kq+2][r0] = rw0.z; Ws[nb][kq+3][r0] = rw0.w;
            Ws[nb][kq+0][r1] = rw1.x; Ws[nb][kq+1][r1] = rw1.y; Ws[nb][kq+2][r1] = rw1.z; Ws[nb][kq+3][r1] = rw1.w;
        }
        __syncthreads();
    }

    const ull_t* bp = (const ull_t*)(bias + n_base + n0);
#pragma unroll
    for (int i = 0; i < 4; ++i) {
        ull_t* crow = (ull_t*)(C + (m_base + mm0 + i) * (long)N + n_base + n0);
#pragma unroll
        for (int p = 0; p < 4; ++p) crow[p] = add2(acc[i][p], bp[p]);
    }
}

// ---------------------------------------------------------------------------
// One recurrent timestep (both directions). 128 blocks:
//   blockIdx.x>>6 = dir (0 fwd, 1 bwd), (blockIdx.x&63)*8 = j0 (h-column slice)
// Block computes gates[64 batch][32 cols] = {i,f,g,o} x 8 cols via
// h_in @ Whh^T (K=512), adds precomputed input gates G[t], then does the
// elementwise LSTM update for its exclusive c/h slice.
// ---------------------------------------------------------------------------
__global__ void __launch_bounds__(128) lstm_step(
    const float* __restrict__ Gf, const float* __restrict__ Gb,
    const float* __restrict__ Wf, const float* __restrict__ Wb,
    const float* __restrict__ mask,
    const float* __restrict__ h_in, float* __restrict__ h_out,
    float* __restrict__ cst, float* __restrict__ outbuf, int s)
{
    __shared__ float Hs[2][16][68];
    __shared__ float Ws[2][16][36];
    __shared__ float Gt[64][34];

    const int tid = threadIdx.x;
    const int dir = blockIdx.x >> 6;
    const int j0  = (blockIdx.x & 63) << 3;
    const int t   = dir ? (255 - s) : s;
    const float* Wh = dir ? Wb : Wf;
    const float* Gp = (dir ? Gb : Gf) + (long)t * 131072;   // + t*B*4H
    const float* hd = h_in + dir * 32768;

    // h load: thread loads 8 consecutive k for one batch row
    const int hb0 = tid >> 1;               // 0..63
    const int hq0 = (tid & 1) * 2;          // float4 col 0 or 2
    const float* hrow = hd + hb0 * 512 + hq0 * 4;
    // W load: 32 gate-rows x 4 float4-cols
    const int wn = tid >> 2;                // 0..31 local gate col
    const int wq = tid & 3;
    const int wcol = (wn >> 3) * 512 + j0 + (wn & 7);
    const float* wrow = Wh + (long)wcol * 512 + wq * 4;

    const int tx = tid & 7;   const int n0 = tx * 4;
    const int ty = tid >> 3;  const int b0 = ty * 4;

    ull_t acc[4][2];
#pragma unroll
    for (int i = 0; i < 4; ++i) { acc[i][0] = 0ull; acc[i][1] = 0ull; }

    float4 rh0, rh1, rw;
    const int kqh = hq0 * 4;
    const int kqw = wq * 4;

    rh0 = *(const float4*)(hrow);
    rh1 = *(const float4*)(hrow + 4);
    rw  = *(const float4*)(wrow);
    Hs[0][kqh+0][hb0] = rh0.x; Hs[0][kqh+1][hb0] = rh0.y; Hs[0][kqh+2][hb0] = rh0.z; Hs[0][kqh+3][hb0] = rh0.w;
    Hs[0][kqh+4][hb0] = rh1.x; Hs[0][kqh+5][hb0] = rh1.y; Hs[0][kqh+6][hb0] = rh1.z; Hs[0][kqh+7][hb0] = rh1.w;
    Ws[0][kqw+0][wn] = rw.x; Ws[0][kqw+1][wn] = rw.y; Ws[0][kqw+2][wn] = rw.z; Ws[0][kqw+3][wn] = rw.w;
    __syncthreads();

    for (int cch = 0; cch < 32; ++cch) {
        const int buf = cch & 1;
        if (cch + 1 < 32) {
            const int k0 = (cch + 1) << 4;
            rh0 = *(const float4*)(hrow + k0);
            rh1 = *(const float4*)(hrow + k0 + 4);
            rw  = *(const float4*)(wrow + k0);
        }
#pragma unroll
        for (int k = 0; k < 16; ++k) {
            float4 a = *(const float4*)&Hs[buf][k][b0];
            ulonglong2 wv = *(const ulonglong2*)&Ws[buf][k][n0];
            ull_t a2[4];
            a2[0] = pk2(a.x, a.x); a2[1] = pk2(a.y, a.y);
            a2[2] = pk2(a.z, a.z); a2[3] = pk2(a.w, a.w);
#pragma unroll
            for (int i = 0; i < 4; ++i) {
                fma2(acc[i][0], a2[i], wv.x);
                fma2(acc[i][1], a2[i], wv.y);
            }
        }
        if (cch + 1 < 32) {
            const int nb = buf ^ 1;
            Hs[nb][kqh+0][hb0] = rh0.x; Hs[nb][kqh+1][hb0] = rh0.y; Hs[nb][kqh+2][hb0] = rh0.z; Hs[nb][kqh+3][hb0] = rh0.w;
            Hs[nb][kqh+4][hb0] = rh1.x; Hs[nb][kqh+5][hb0] = rh1.y; Hs[nb][kqh+6][hb0] = rh1.z; Hs[nb][kqh+7][hb0] = rh1.w;
            Ws[nb][kqw+0][wn] = rw.x; Ws[nb][kqw+1][wn] = rw.y; Ws[nb][kqw+2][wn] = rw.z; Ws[nb][kqw+3][wn] = rw.w;
        }
        __syncthreads();
    }

    // gate tile -> smem
#pragma unroll
    for (int i = 0; i < 4; ++i) {
        *(ull_t*)&Gt[b0 + i][n0]     = acc[i][0];
        *(ull_t*)&Gt[b0 + i][n0 + 2] = acc[i][1];
    }
    __syncthreads();

    // elementwise LSTM update: 512 (b, jj) cells, 4 per thread
#pragma unroll
    for (int i = 0; i < 4; ++i) {
        const int u  = (tid << 2) | i;
        const int b  = u >> 3;
        const int jj = u & 7;
        const long gb = (long)b * 2048 + j0 + jj;
        float ig = Gt[b][jj]      + Gp[gb];
        float fg = Gt[b][8 + jj]  + Gp[gb + 512];
        float gg = Gt[b][16 + jj] + Gp[gb + 1024];
        float og = Gt[b][24 + jj] + Gp[gb + 1536];
        const float mv = mask[t * 64 + b];
        const int ci = dir * 32768 + b * 512 + j0 + jj;
        const float cold = cst[ci];
        const float cn = (sigf(fg) * cold + sigf(ig) * tanhf(gg)) * mv;
        const float hn = sigf(og) * tanhf(cn) * mv;
        cst[ci]   = cn;
        h_out[ci] = hn;
        outbuf[(long)(t * 64 + b) * 1024 + dir * 512 + j0 + jj] = hn;
    }
}

// ---------------------------------------------------------------------------
// small kernels
// ---------------------------------------------------------------------------
__global__ void init_state(const float* __restrict__ fi, const float* __restrict__ bi,
                           float* __restrict__ h, float* __restrict__ c)
{
    const int idx = blockIdx.x * 256 + threadIdx.x;      // 0..65535
    const int dir = idx >> 15;
    const int j = idx & 511;
    const float* iv = dir ? bi : fi;
    h[idx] = iv[j];
    c[idx] = iv[512 + j];
}

__global__ void finalize_state(const float* __restrict__ h, const float* __restrict__ c,
                               float* __restrict__ oh, float* __restrict__ oc)
{
    const int idx = blockIdx.x * 256 + threadIdx.x;      // 0..65535
    oh[idx] = h[idx];
    oc[idx] = c[idx];
}

__global__ void highway_elem(const float* __restrict__ P, const float* __restrict__ o,
                             const float* __restrict__ ip, float* __restrict__ d)
{
    const int idx = blockIdx.x * 256 + threadIdx.x;      // covers 16777216
    const float g = sigf(P[idx]);
    d[idx] = g * o[idx] + (1.0f - g) * ip[idx];
}

// ---------------------------------------------------------------------------
// host orchestration (captured into the graph: ~784 kernel nodes)
// ---------------------------------------------------------------------------
extern "C" void kernel_launch(void* const* d_in, const int* in_sizes, int n_in,
                              void* d_out, int out_size)
{
    (void)in_sizes; (void)n_in; (void)out_size;
    const float* x     = (const float*)d_in[0];
    const float* mask  = (const float*)d_in[1];
    const float* fWih0 = (const float*)d_in[2];
    const float* fWihR = (const float*)d_in[3];
    const float* fWhh  = (const float*)d_in[4];
    const float* fb    = (const float*)d_in[5];
    const float* bWih0 = (const float*)d_in[6];
    const float* bWihR = (const float*)d_in[7];
    const float* bWhh  = (const float*)d_in[8];
    const float* bb    = (const float*)d_in[9];
    const float* fini  = (const float*)d_in[10];
    const float* bini  = (const float*)d_in[11];
    const float* pW    = (const float*)d_in[12];
    const float* pb    = (const float*)d_in[13];
    float* out = (float*)d_out;

    float *Gf, *Gb, *bufA, *bufB, *hst, *cst;
    cudaGetSymbolAddress((void**)&Gf,   g_Gf);
    cudaGetSymbolAddress((void**)&Gb,   g_Gb);
    cudaGetSymbolAddress((void**)&bufA, g_bufA);
    cudaGetSymbolAddress((void**)&bufB, g_bufB);
    cudaGetSymbolAddress((void**)&hst,  g_hst);
    cudaGetSymbolAddress((void**)&cst,  g_cst);

    const long HN_OFF = 16777216;                 // T*B*2H
    const long CN_OFF = 16777216 + 196608;        // + 6*B*H

    const float* inp = x;
    float* outp = bufA;
    for (int l = 0; l < 3; ++l) {
        const int Kin = (l == 0) ? 512 : 1024;
        const float* Wfi = (l == 0) ? fWih0 : fWihR + (size_t)(l - 1) * 2048 * 1024;
        const float* Wbi = (l == 0) ? bWih0 : bWihR + (size_t)(l - 1) * 2048 * 1024;

        // input-gate precompute: G = inp @ Wih^T + b   (M=16384, N=2048)
        gemm_nt_bias<<<dim3(32, 256), 128>>>(inp, Wfi, fb + l * 2048, Gf, 2048, Kin);
        gemm_nt_bias<<<dim3(32, 256), 128>>>(inp, Wbi, bb + l * 2048, Gb, 2048, Kin);

        init_state<<<256, 256>>>(fini + l * 1024, bini + l * 1024, hst, cst);

        for (int s = 0; s < 256; ++s) {
            lstm_step<<<128, 128>>>(Gf, Gb,
                                    fWhh + (size_t)l * 2048 * 512,
                                    bWhh + (size_t)l * 2048 * 512,
                                    mask,
                                    hst + (s & 1) * 65536,
                                    hst + ((s + 1) & 1) * 65536,
                                    cst, outp, s);
        }
        // after 256 steps final h lives in parity 0
        finalize_state<<<256, 256>>>(hst, cst, out + HN_OFF + l * 65536, out + CN_OFF + l * 65536);

        if (l > 0) {
            // highway gate: P = outp @ projW^T + projb   (N=K=1024); reuse Gf as P
            gemm_nt_bias<<<dim3(16, 256), 128>>>(outp, pW + (size_t)(l - 1) * 1048576,
                                                 pb + (l - 1) * 1024, Gf, 1024, 1024);
            highway_elem<<<65536, 256>>>(Gf, outp, inp, (l == 2) ? out : outp);
        }
        inp = outp;
        outp = (outp == bufA) ? bufB : bufA;
    }
}

// round 9
// speedup vs baseline: 1.1144x; 1.1144x over previous
#include <cuda_runtime.h>
#include <math.h>

typedef unsigned long long ull_t;

// ---------------------------------------------------------------------------
// packed f32x2 helpers
// ---------------------------------------------------------------------------
__device__ __forceinline__ ull_t pk2(float x, float y) {
    ull_t r;
    asm("mov.b64 %0, {%1, %2};" : "=l"(r) : "r"(__float_as_uint(x)), "r"(__float_as_uint(y)));
    return r;
}
__device__ __forceinline__ void fma2(ull_t& d, ull_t a, ull_t b) {
    asm("fma.rn.f32x2 %0, %1, %2, %0;" : "+l"(d) : "l"(a), "l"(b));
}
__device__ __forceinline__ ull_t add2(ull_t a, ull_t b) {
    ull_t r;
    asm("add.rn.f32x2 %0, %1, %2;" : "=l"(r) : "l"(a), "l"(b));
    return r;
}
__device__ __forceinline__ float sigf(float x) { return 1.0f / (1.0f + expf(-x)); }

// ---------------------------------------------------------------------------
// scratch (device globals — no allocation allowed)
// ---------------------------------------------------------------------------
__device__ float g_Gf[33554432];     // [T*B, 2048] fwd input-gate precompute (also proj buffer)
__device__ float g_Gb[33554432];     // [T*B, 2048] bwd
__device__ float g_bufA[16777216];   // [T*B, 1024] ping
__device__ float g_bufB[16777216];   // [T*B, 1024] pong
__device__ float g_hst[131072];      // h double buffer: [parity][dir][64][512]
__device__ volatile int g_bar[768];  // grid-barrier slots (self-resetting)

// ---------------------------------------------------------------------------
// grid barrier: slot-indexed, 128 arrivals; releaser resets the previous slot
// (by the time slot s completes, every block has passed slot s-1 and will
// never read it again). Layer-l launch uses slots [l*256, l*256+256); the
// first release of layer 0 resets slot 767 left over from the previous replay.
// ---------------------------------------------------------------------------
__device__ __forceinline__ void grid_bar(int slot) {
    __syncthreads();
    if (threadIdx.x == 0) {
        __threadfence();
        int old = atomicAdd((int*)&g_bar[slot], 1);
        if (old == 127) {
            int prev = (slot == 0) ? 767 : slot - 1;
            g_bar[prev] = 0;
        } else {
            while (g_bar[slot] < 128) { }
        }
        __threadfence();
    }
    __syncthreads();
}

// ---------------------------------------------------------------------------
// C[M,N] = A[M,K] @ W[N,K]^T + bias[N]   (precompute / projection GEMM)
// ---------------------------------------------------------------------------
__global__ void __launch_bounds__(128) gemm_nt_bias(
    const float* __restrict__ A, const float* __restrict__ W,
    const float* __restrict__ bias, float* __restrict__ C,
    int N, int K)
{
    __shared__ float As[2][16][68];
    __shared__ float Ws[2][16][68];

    const int tid = threadIdx.x;
    const long m_base = (long)blockIdx.y * 64;
    const long n_base = (long)blockIdx.x * 64;

    const int r0 = tid >> 2;
    const int q0 = tid & 3;
    const int r1 = r0 + 32;

    const float* Arow0 = A + (m_base + r0) * (long)K + q0 * 4;
    const float* Arow1 = A + (m_base + r1) * (long)K + q0 * 4;
    const float* Wrow0 = W + (n_base + r0) * (long)K + q0 * 4;
    const float* Wrow1 = W + (n_base + r1) * (long)K + q0 * 4;

    const int tx  = tid & 7;
    const int ty  = tid >> 3;
    const int n0  = tx * 8;
    const int mm0 = ty * 4;

    ull_t acc[4][4];
#pragma unroll
    for (int i = 0; i < 4; ++i)
#pragma unroll
        for (int p = 0; p < 4; ++p) acc[i][p] = 0ull;

    float4 ra0, ra1, rw0, rw1;
    const int kq = q0 * 4;

    ra0 = *(const float4*)(Arow0);
    ra1 = *(const float4*)(Arow1);
    rw0 = *(const float4*)(Wrow0);
    rw1 = *(const float4*)(Wrow1);
    As[0][kq+0][r0] = ra0.x; As[0][kq+1][r0] = ra0.y; As[0][kq+2][r0] = ra0.z; As[0][kq+3][r0] = ra0.w;
    As[0][kq+0][r1] = ra1.x; As[0][kq+1][r1] = ra1.y; As[0][kq+2][r1] = ra1.z; As[0][kq+3][r1] = ra1.w;
    Ws[0][kq+0][r0] = rw0.x; Ws[0][kq+1][r0] = rw0.y; Ws[0][kq+2][r0] = rw0.z; Ws[0][kq+3][r0] = rw0.w;
    Ws[0][kq+0][r1] = rw1.x; Ws[0][kq+1][r1] = rw1.y; Ws[0][kq+2][r1] = rw1.z; Ws[0][kq+3][r1] = rw1.w;
    __syncthreads();

    const int nk = K >> 4;
    for (int cch = 0; cch < nk; ++cch) {
        const int buf = cch & 1;
        if (cch + 1 < nk) {
            const int k0 = (cch + 1) << 4;
            ra0 = *(const float4*)(Arow0 + k0);
            ra1 = *(const float4*)(Arow1 + k0);
            rw0 = *(const float4*)(Wrow0 + k0);
            rw1 = *(const float4*)(Wrow1 + k0);
        }
#pragma unroll
        for (int k = 0; k < 16; ++k) {
            float4 a = *(const float4*)&As[buf][k][mm0];
            ulonglong2 wv0 = *(const ulonglong2*)&Ws[buf][k][n0];
            ulonglong2 wv1 = *(const ulonglong2*)&Ws[buf][k][n0 + 4];
            ull_t a2[4];
            a2[0] = pk2(a.x, a.x); a2[1] = pk2(a.y, a.y);
            a2[2] = pk2(a.z, a.z); a2[3] = pk2(a.w, a.w);
            ull_t wr[4] = {wv0.x, wv0.y, wv1.x, wv1.y};
#pragma unroll
            for (int i = 0; i < 4; ++i) {
                fma2(acc[i][0], a2[i], wr[0]);
                fma2(acc[i][1], a2[i], wr[1]);
                fma2(acc[i][2], a2[i], wr[2]);
                fma2(acc[i][3], a2[i], wr[3]);
            }
        }
        if (cch + 1 < nk) {
            const int nb = buf ^ 1;
            As[nb][kq+0][r0] = ra0.x; As[nb][kq+1][r0] = ra0.y; As[nb][kq+2][r0] = ra0.z; As[nb][kq+3][r0] = ra0.w;
            As[nb][kq+0][r1] = ra1.x; As[nb][kq+1][r1] = ra1.y; As[nb][kq+2][r1] = ra1.z; As[nb][kq+3][r1] = ra1.w;
            Ws[nb][kq+0][r0] = rw0.x; Ws[nb][kq+1][r0] = rw0.y; Ws[nb][kq+2][r0] = rw0.z; Ws[nb][kq+3][r0] = rw0.w;
            Ws[nb][kq+0][r1] = rw1.x; Ws[nb][kq+1][r1] = rw1.y; Ws[nb][kq+2][r1] = rw1.z; Ws[nb][kq+3][r1] = rw1.w;
        }
        __syncthreads();
    }

    const ull_t* bp = (const ull_t*)(bias + n_base + n0);
#pragma unroll
    for (int i = 0; i < 4; ++i) {
        ull_t* crow = (ull_t*)(C + (m_base + mm0 + i) * (long)N + n_base + n0);
#pragma unroll
        for (int p = 0; p < 4; ++p) crow[p] = add2(acc[i][p], bp[p]);
    }
}

// ---------------------------------------------------------------------------
// Persistent bi-LSTM layer kernel: 128 blocks x 256 threads, all co-resident.
//   block b: dir = b>>6, j0 = (b&63)*8   (owns h columns j0..j0+7 of its dir)
// Whh slice (32 gate rows x 512) lives in smem for all 256 steps.
// Per step: stage h (pre-duplicated f32x2) -> GEMM -> gate exchange ->
// elementwise update (c in registers) -> write h ping-pong + layer output.
// ---------------------------------------------------------------------------
__global__ void __launch_bounds__(256, 1) lstm_layer(
    const float* __restrict__ Gf, const float* __restrict__ Gb,
    const float* __restrict__ Wf, const float* __restrict__ Wb,
    const float* __restrict__ mask,
    float* __restrict__ hglob, float* __restrict__ outbuf,
    float* __restrict__ hn_out, float* __restrict__ cn_out,
    const float* __restrict__ fini_l, const float* __restrict__ bini_l,
    int slotBase)
{
    extern __shared__ char smem_raw[];
    float* Wsh = (float*)smem_raw;                           // [512][32]  = 65536 B
    ull_t* Hs2 = (ull_t*)(smem_raw + 65536);                 // [2][32][66] ull = 33792 B
    float* Gt  = (float*)(smem_raw + 65536 + 33792);         // [64][34]   = 8704 B

    const int tid = threadIdx.x;
    const int dir = blockIdx.x >> 6;
    const int j0  = (blockIdx.x & 63) << 3;
    const float* Wh   = dir ? Wb : Wf;
    const float* Gdir = dir ? Gb : Gf;
    const float* iv   = dir ? bini_l : fini_l;

    // ---- load Whh slice transposed into smem: Wsh[k][n] = Wh[row(n)][k] ----
    {
        const int n  = tid >> 3;                 // 0..31 local gate row
        const int kq = tid & 7;
        const int grow = (n >> 3) * 512 + j0 + (n & 7);
        const float* wr = Wh + (size_t)grow * 512 + kq * 4;
#pragma unroll
        for (int i = 0; i < 16; ++i) {
            float4 w = *(const float4*)(wr + i * 32);
            const int k = kq * 4 + i * 32;
            Wsh[(k + 0) * 32 + n] = w.x;
            Wsh[(k + 1) * 32 + n] = w.y;
            Wsh[(k + 2) * 32 + n] = w.z;
            Wsh[(k + 3) * 32 + n] = w.w;
        }
    }

    // ---- compute / staging / elementwise thread mappings ----
    const int tx = tid & 7;   const int n0 = tx * 4;     // 4 gate rows (2 ull)
    const int ty = tid >> 3;  const int b0 = ty * 2;     // 2 batch rows
    const int sb  = tid >> 2; const int skq = tid & 3;   // staging: batch, k-quad
    const int eb  = tid >> 2;                            // elementwise batch
    const int ejj = (tid * 2) & 7;                       // elementwise col (even)

    // ---- init: h0 to global parity 0, c0 to registers ----
    float creg[2], hlast[2];
    {
        float h0a = iv[j0 + ejj];
        float h0b = iv[j0 + ejj + 1];
        creg[0] = iv[512 + j0 + ejj];
        creg[1] = iv[512 + j0 + ejj + 1];
        float* hp = hglob + dir * 32768 + eb * 512 + j0 + ejj;
        __stcg(hp,     h0a);
        __stcg(hp + 1, h0b);
        hlast[0] = h0a; hlast[1] = h0b;
    }

    int par = 0;
    for (int s = 0; s < 256; ++s) {
        const int t = dir ? (255 - s) : s;

        // prefetch G[t] gate rows + mask (consumed ~9000 cycles later)
        float gpr[2][4], mv;
        {
            const float* gp = Gdir + (size_t)t * 131072 + (size_t)eb * 2048 + j0 + ejj;
            mv = __ldcg(&mask[t * 64 + eb]);
#pragma unroll
            for (int c = 0; c < 2; ++c)
#pragma unroll
                for (int q = 0; q < 4; ++q)
                    gpr[c][q] = __ldcg(gp + q * 512 + c);
        }

        grid_bar(slotBase + s);     // h[par] fully written by all blocks

        const float* hbase = hglob + par * 65536 + dir * 32768;
        const float* hsrc  = hbase + sb * 512 + skq * 4;

        ull_t a00 = 0, a01 = 0, a10 = 0, a11 = 0;

        // preload tile 0
        float4 r0 = __ldcg((const float4*)(hsrc));
        float4 r1 = __ldcg((const float4*)(hsrc + 16));
        {
            ull_t* Hb = Hs2;
            Hb[(skq * 4 + 0) * 66 + sb] = pk2(r0.x, r0.x);
            Hb[(skq * 4 + 1) * 66 + sb] = pk2(r0.y, r0.y);
            Hb[(skq * 4 + 2) * 66 + sb] = pk2(r0.z, r0.z);
            Hb[(skq * 4 + 3) * 66 + sb] = pk2(r0.w, r0.w);
            Hb[(16 + skq * 4 + 0) * 66 + sb] = pk2(r1.x, r1.x);
            Hb[(16 + skq * 4 + 1) * 66 + sb] = pk2(r1.y, r1.y);
            Hb[(16 + skq * 4 + 2) * 66 + sb] = pk2(r1.z, r1.z);
            Hb[(16 + skq * 4 + 3) * 66 + sb] = pk2(r1.w, r1.w);
        }
        __syncthreads();

        for (int tt = 0; tt < 16; ++tt) {
            const int buf = tt & 1;
            if (tt < 15) {
                const int k0 = (tt + 1) * 32;
                r0 = __ldcg((const float4*)(hsrc + k0));
                r1 = __ldcg((const float4*)(hsrc + k0 + 16));
            }
            const ull_t* Hb = Hs2 + buf * 2112;
            const float* WB = Wsh + tt * 1024;           // (tt*32)*32
#pragma unroll
            for (int k = 0; k < 32; ++k) {
                ulonglong2 a = *(const ulonglong2*)&Hb[k * 66 + b0];
                ulonglong2 w = *(const ulonglong2*)&WB[k * 32 + n0];
                fma2(a00, a.x, w.x); fma2(a01, a.x, w.y);
                fma2(a10, a.y, w.x); fma2(a11, a.y, w.y);
            }
            if (tt < 15) {
                ull_t* Hn = Hs2 + (buf ^ 1) * 2112;
                Hn[(skq * 4 + 0) * 66 + sb] = pk2(r0.x, r0.x);
                Hn[(skq * 4 + 1) * 66 + sb] = pk2(r0.y, r0.y);
                Hn[(skq * 4 + 2) * 66 + sb] = pk2(r0.z, r0.z);
                Hn[(skq * 4 + 3) * 66 + sb] = pk2(r0.w, r0.w);
                Hn[(16 + skq * 4 + 0) * 66 + sb] = pk2(r1.x, r1.x);
                Hn[(16 + skq * 4 + 1) * 66 + sb] = pk2(r1.y, r1.y);
                Hn[(16 + skq * 4 + 2) * 66 + sb] = pk2(r1.z, r1.z);
                Hn[(16 + skq * 4 + 3) * 66 + sb] = pk2(r1.w, r1.w);
            }
            __syncthreads();
        }

        // gate tile exchange
        *(ull_t*)&Gt[b0 * 34 + n0]           = a00;
        *(ull_t*)&Gt[b0 * 34 + n0 + 2]       = a01;
        *(ull_t*)&Gt[(b0 + 1) * 34 + n0]     = a10;
        *(ull_t*)&Gt[(b0 + 1) * 34 + n0 + 2] = a11;
        __syncthreads();

        // elementwise LSTM update for 2 owned cells
        float* hnext = hglob + (par ^ 1) * 65536 + dir * 32768;
#pragma unroll
        for (int c = 0; c < 2; ++c) {
            const int jj = ejj + c;
            float ig = Gt[eb * 34 + jj]      + gpr[c][0];
            float fg = Gt[eb * 34 + 8 + jj]  + gpr[c][1];
            float gg = Gt[eb * 34 + 16 + jj] + gpr[c][2];
            float og = Gt[eb * 34 + 24 + jj] + gpr[c][3];
            float cn = (sigf(fg) * creg[c] + sigf(ig) * tanhf(gg)) * mv;
            float hn = sigf(og) * tanhf(cn) * mv;
            creg[c] = cn; hlast[c] = hn;
            __stcg(&hnext[eb * 512 + j0 + jj], hn);
            outbuf[(size_t)(t * 64 + eb) * 1024 + dir * 512 + j0 + jj] = hn;
        }
        par ^= 1;
    }

    // final h_n / c_n
#pragma unroll
    for (int c = 0; c < 2; ++c) {
        const int off = dir * 32768 + eb * 512 + j0 + ejj + c;
        hn_out[off] = hlast[c];
        cn_out[off] = creg[c];
    }
}

// ---------------------------------------------------------------------------
__global__ void highway_elem(const float* __restrict__ P, const float* __restrict__ o,
                             const float* __restrict__ ip, float* __restrict__ d)
{
    const int idx = blockIdx.x * 256 + threadIdx.x;
    const float g = sigf(P[idx]);
    d[idx] = g * o[idx] + (1.0f - g) * ip[idx];
}

// ---------------------------------------------------------------------------
extern "C" void kernel_launch(void* const* d_in, const int* in_sizes, int n_in,
                              void* d_out, int out_size)
{
    (void)in_sizes; (void)n_in; (void)out_size;
    const float* x     = (const float*)d_in[0];
    const float* mask  = (const float*)d_in[1];
    const float* fWih0 = (const float*)d_in[2];
    const float* fWihR = (const float*)d_in[3];
    const float* fWhh  = (const float*)d_in[4];
    const float* fb    = (const float*)d_in[5];
    const float* bWih0 = (const float*)d_in[6];
    const float* bWihR = (const float*)d_in[7];
    const float* bWhh  = (const float*)d_in[8];
    const float* bb    = (const float*)d_in[9];
    const float* fini  = (const float*)d_in[10];
    const float* bini  = (const float*)d_in[11];
    const float* pW    = (const float*)d_in[12];
    const float* pb    = (const float*)d_in[13];
    float* out = (float*)d_out;

    float *Gf, *Gb, *bufA, *bufB, *hst;
    cudaGetSymbolAddress((void**)&Gf,   g_Gf);
    cudaGetSymbolAddress((void**)&Gb,   g_Gb);
    cudaGetSymbolAddress((void**)&bufA, g_bufA);
    cudaGetSymbolAddress((void**)&bufB, g_bufB);
    cudaGetSymbolAddress((void**)&hst,  g_hst);

    const int SMEM_LSTM = 65536 + 33792 + 8704;   // 108032 B
    cudaFuncSetAttribute(lstm_layer, cudaFuncAttributeMaxDynamicSharedMemorySize, SMEM_LSTM);

    const long HN_OFF = 16777216;                 // T*B*2H
    const long CN_OFF = 16777216 + 196608;        // + 6*B*H

    const float* inp = x;
    float* outp = bufA;
    for (int l = 0; l < 3; ++l) {
        const int Kin = (l == 0) ? 512 : 1024;
        const float* Wfi = (l == 0) ? fWih0 : fWihR + (size_t)(l - 1) * 2048 * 1024;
        const float* Wbi = (l == 0) ? bWih0 : bWihR + (size_t)(l - 1) * 2048 * 1024;

        gemm_nt_bias<<<dim3(32, 256), 128>>>(inp, Wfi, fb + l * 2048, Gf, 2048, Kin);
        gemm_nt_bias<<<dim3(32, 256), 128>>>(inp, Wbi, bb + l * 2048, Gb, 2048, Kin);

        lstm_layer<<<128, 256, SMEM_LSTM>>>(
            Gf, Gb,
            fWhh + (size_t)l * 1048576, bWhh + (size_t)l * 1048576,
            mask, hst, outp,
            out + HN_OFF + l * 65536, out + CN_OFF + l * 65536,
            fini + l * 1024, bini + l * 1024,
            l * 256);

        if (l > 0) {
            gemm_nt_bias<<<dim3(16, 256), 128>>>(outp, pW + (size_t)(l - 1) * 1048576,
                                                 pb + (l - 1) * 1024, Gf, 1024, 1024);
            highway_elem<<<65536, 256>>>(Gf, outp, inp, (l == 2) ? out : outp);
        }
        inp = outp;
        outp = (outp == bufA) ? bufB : bufA;
    }
}